// round 10
// baseline (speedup 1.0000x reference)
#include <cuda_runtime.h>
#include <math.h>
#include <stdint.h>

// Problem dims
#define Bb   256
#define Ss   512
#define Hh   256
#define OUTD 3
#define NST  64
#define INW  259
#define G4   (4*Hh)
#define TR   16
#define NTILES (Ss/TR)   // 32

// Output layout
#define OFF_PRED 0
#define OFF_HID  (Bb*NST*OUTD)          // 49152
#define OFF_ATT  (OFF_HID + Bb*Hh)      // 114688

// Persistent device state
__device__ float g_hbuf[2][Bb*Hh];
__device__ float g_c[Bb*Hh];
__device__ float g_x[Bb*OUTD];
__device__ float g_ctx[Bb*Hh];
__device__ float g_WgT[512*G4];    // [k][col], col = (j'>>1)*8 + gate*2 + (j'&1)
__device__ float g_Wx[G4*OUTD];    // indexed by n = gate*256 + j'
__device__ float g_bias[G4];
__device__ float g_M[Hh*Hh];       // [k][j]
__device__ float g_vb[Hh];

__device__ __forceinline__ float warp_sum(float v){
  #pragma unroll
  for (int o = 16; o; o >>= 1) v += __shfl_xor_sync(0xffffffffu, v, o);
  return v;
}
__device__ __forceinline__ float sigmoidf_(float x){ return 1.f/(1.f+expf(-x)); }

__device__ __forceinline__ uint32_t smem_u32(const void* p){
  return (uint32_t)__cvta_generic_to_shared(p);
}
__device__ __forceinline__ void cp16(uint32_t dst, const void* src){
  asm volatile("cp.async.cg.shared.global [%0], [%1], 16;" :: "r"(dst), "l"(src));
}
#define CP_COMMIT() asm volatile("cp.async.commit_group;")
#define CP_WAIT(n)  asm volatile("cp.async.wait_group %0;" :: "n"(n))

__device__ __forceinline__ void fma2(unsigned long long &d, unsigned long long a, unsigned long long b){
  asm("fma.rn.f32x2 %0, %1, %2, %3;" : "=l"(d) : "l"(a), "l"(b), "l"(d));
}
__device__ __forceinline__ unsigned long long dup2(float v){
  unsigned long long r; uint32_t u = __float_as_uint(v);
  asm("mov.b64 %0, {%1, %1};" : "=l"(r) : "r"(u));
  return r;
}
__device__ __forceinline__ float2 unpack2(unsigned long long v){
  uint32_t lo, hi;
  asm("mov.b64 {%0, %1}, %2;" : "=r"(lo), "=r"(hi) : "l"(v));
  return make_float2(__uint_as_float(lo), __uint_as_float(hi));
}

// ---------------------------------------------------------------- init/pack/prep
__global__ void k_init(const float* __restrict__ eh, const float* __restrict__ ec){
  int i = blockIdx.x*blockDim.x + threadIdx.x;
  if (i < Bb*Hh){ g_hbuf[0][i] = eh[i]; g_c[i] = ec[i]; }
  if (i < Bb*OUTD) g_x[i] = 0.f;
}

__global__ void k_pack(const float* __restrict__ Wih, const float* __restrict__ Whh,
                       const float* __restrict__ bih, const float* __restrict__ bhh){
  int j = blockIdx.x;   // 0..1023, original row: gate g = j>>8, j' = j&255
  int k = threadIdx.x;  // 0..511
  float val = (k < Hh) ? Wih[j*INW + OUTD + k] : Whh[j*Hh + (k - Hh)];
  int g = j >> 8, jp = j & 255;
  int col = (jp >> 1)*8 + g*2 + (jp & 1);
  g_WgT[(size_t)k*G4 + col] = val;
  if (k < OUTD) g_Wx[j*OUTD + k] = Wih[j*INW + k];
  if (k == 0)   g_bias[j] = bih[j] + bhh[j];
}

__global__ void k_prep(const float* __restrict__ Wa, const float* __restrict__ ba,
                       const float* __restrict__ Ua){
  int kk = blockIdx.x, j = threadIdx.x;
  float a = 0.f;
  if (kk < Hh){
    #pragma unroll 4
    for (int g = 0; g < Hh; g++) a = fmaf(Wa[g*Hh + kk], Ua[g*Hh + j], a);
    g_M[kk*Hh + j] = a;
  } else {
    #pragma unroll 4
    for (int g = 0; g < Hh; g++) a = fmaf(ba[g], Ua[g*Hh + j], a);
    g_vb[j] = a;
  }
}

// ---------------------------------------------------------------- attention megaphase
// 1 block per batch. Prologue (under cp.async): pred(h)->x/out, v = h@M+vb.
// Then single-slice flash attention over 512 rows; writes FINAL weights + ctx.
#define ATTN_DSM (3*TR*Hh*4)   // 49152
__global__ void __launch_bounds__(256)
k_attn(const float* __restrict__ enc, const float* __restrict__ hold,
       const float* __restrict__ Wo, const float* __restrict__ bo,
       float* __restrict__ out, int t){
  extern __shared__ float tb[];          // [3][TR][Hh]
  __shared__ float h_s[Hh];
  __shared__ float v_s[Hh];
  __shared__ float ctx_s[Hh];
  __shared__ float wbuf[Ss];
  __shared__ float tsc[TR];
  __shared__ float tmaxs[NTILES];
  __shared__ float red0;
  int b = blockIdx.x, tid = threadIdx.x, wid = tid >> 5, lane = tid & 31;
  const float* encb = enc + (size_t)b*Ss*Hh;

  auto issue = [&](int ti){
    const float4* src = (const float4*)(encb + (size_t)ti*TR*Hh);
    uint32_t dst = smem_u32(tb + (ti % 3)*TR*Hh);
    #pragma unroll
    for (int i = 0; i < 4; i++){
      int idx = tid + 256*i;
      cp16(dst + idx*16, src + idx);
    }
    CP_COMMIT();
  };

  h_s[tid] = hold[b*Hh + tid];
  issue(0); issue(1); issue(2);
  ctx_s[tid] = 0.f;
  __syncthreads();

  // pred from h_t -> autoregressive x + output for step t-1
  if (wid < 3){
    float a = 0.f;
    #pragma unroll
    for (int k = lane; k < Hh; k += 32) a = fmaf(h_s[k], Wo[wid*Hh + k], a);
    a = warp_sum(a);
    if (!lane && t > 0){
      float p = a + bo[wid];
      out[OFF_PRED + ((size_t)b*NST + (t-1))*OUTD + wid] = p;
      g_x[b*OUTD + wid] = p;
    }
  }
  // v = h @ M + vb (coalesced L2 reads of M; overlaps enc prefetch)
  {
    float acc = g_vb[tid];
    #pragma unroll 16
    for (int k = 0; k < Hh; k++) acc = fmaf(h_s[k], g_M[k*Hh + tid], acc);
    v_s[tid] = acc;
  }
  __syncthreads();

  float m_run = -3.0e38f, l_run = 0.f;
  for (int ti = 0; ti < NTILES; ti++){
    int rem = NTILES - 1 - ti;
    if (rem >= 2)      CP_WAIT(2);
    else if (rem == 1) CP_WAIT(1);
    else               CP_WAIT(0);
    __syncthreads();
    const float* tile = tb + (ti % 3)*TR*Hh;

    // scores: 2 rows per warp
    #pragma unroll
    for (int r = 0; r < 2; r++){
      int s = wid*2 + r;
      float acc = 0.f;
      #pragma unroll
      for (int k = 0; k < 8; k++) acc = fmaf(tile[s*Hh + lane + 32*k], v_s[lane + 32*k], acc);
      acc = warp_sum(acc);
      if (!lane) tsc[s] = acc;
    }
    __syncthreads();

    float mt = tsc[0];
    #pragma unroll
    for (int s = 1; s < TR; s++) mt = fmaxf(mt, tsc[s]);
    float m_new = fmaxf(m_run, mt);
    float scale = expf(m_run - m_new);

    if (wid == 0){
      float e = (lane < TR) ? expf(tsc[lane] - m_new) : 0.f;
      if (lane < TR) wbuf[ti*TR + lane] = e;
      float es = warp_sum(e);
      if (!lane){ red0 = es; tmaxs[ti] = m_new; }
    }
    __syncthreads();
    l_run = l_run * scale + red0;
    m_run = m_new;

    float c = ctx_s[tid] * scale;
    #pragma unroll
    for (int s = 0; s < TR; s++) c = fmaf(wbuf[ti*TR + s], tile[s*Hh + tid], c);
    ctx_s[tid] = c;
    __syncthreads();                     // tile (ti%3) free
    if (ti + 3 < NTILES) issue(ti + 3);
  }

  float inv = 1.f / l_run;
  g_ctx[b*Hh + tid] = ctx_s[tid] * inv;
  float* att = out + OFF_ATT + ((size_t)b*NST + t)*Ss;
  att[tid]        = wbuf[tid]       * expf(tmaxs[tid >> 4] - m_run)       * inv;
  att[tid + 256]  = wbuf[tid + 256] * expf(tmaxs[(tid + 256) >> 4] - m_run) * inv;
}

// ---------------------------------------------------------------- gates GEMM + fused LSTM (f32x2)
// 128 blocks x 256 thr: jt = p&15 (16 j'), mt = p>>4 (32 batches).
// Thread (tx 0..7, ty 0..31): 1 batch, j-pair j0+tx*2, all 4 gates.
#define GKT 32
__global__ void __launch_bounds__(256)
k_gl(const float* __restrict__ hold, float* __restrict__ hnew){
  __shared__ __align__(16) float As[2][GKT*36];
  __shared__ __align__(16) float Bs[2][GKT*64];
  int p = blockIdx.x, tid = threadIdx.x;
  int jt = p & 15, mt = p >> 4;
  int j0 = jt * 16, m0 = mt * 32;

  auto issueB = [&](int it){
    int kt = it*GKT, pb = it & 1;
    #pragma unroll
    for (int i = 0; i < 2; i++){
      int idx = tid + 256*i;            // 512 cp16 (32 rows x 64 floats)
      int row = idx >> 4, c4 = (idx & 15) << 2;
      cp16(smem_u32(&Bs[pb][row*64 + c4]),
           g_WgT + (size_t)(kt + row)*G4 + jt*64 + c4);
    }
    CP_COMMIT();
  };
  auto loadA = [&](int it){
    int kt = it*GKT, pb = it & 1;
    int rr = tid >> 3, c4 = (tid & 7) << 2;   // batch, local k
    int bb = m0 + rr, k = kt + c4;
    float4 a4 = (k < Hh) ? *(const float4*)(g_ctx + bb*Hh + k)
                         : *(const float4*)(hold  + bb*Hh + (k - Hh));
    As[pb][(c4+0)*36 + rr] = a4.x;
    As[pb][(c4+1)*36 + rr] = a4.y;
    As[pb][(c4+2)*36 + rr] = a4.z;
    As[pb][(c4+3)*36 + rr] = a4.w;
  };

  int tx = tid & 7, ty = tid >> 3;
  unsigned long long acc2[4] = {};      // per gate: f32x2 over (j_lo, j_hi)

  issueB(0); loadA(0);
  for (int it = 0; it < 16; it++){
    if (it < 15){ issueB(it+1); loadA(it+1); CP_WAIT(1); }
    else          CP_WAIT(0);
    __syncthreads();
    int pb = it & 1;
    #pragma unroll
    for (int kk = 0; kk < GKT; kk++){
      unsigned long long a = dup2(As[pb][kk*36 + ty]);
      ulonglong2 b01 = *(const ulonglong2*)&Bs[pb][kk*64 + tx*8];
      ulonglong2 b23 = *(const ulonglong2*)&Bs[pb][kk*64 + tx*8 + 4];
      fma2(acc2[0], a, b01.x);
      fma2(acc2[1], a, b01.y);
      fma2(acc2[2], a, b23.x);
      fma2(acc2[3], a, b23.y);
    }
    __syncthreads();
  }

  // fused LSTM: this thread owns batch b, j in {j0+tx*2, j0+tx*2+1}, all gates
  int b = m0 + ty;
  float x0 = g_x[b*OUTD+0], x1 = g_x[b*OUTD+1], x2 = g_x[b*OUTD+2];
  float2 pg[4];
  #pragma unroll
  for (int g = 0; g < 4; g++) pg[g] = unpack2(acc2[g]);
  #pragma unroll
  for (int jl = 0; jl < 2; jl++){
    int j = j0 + tx*2 + jl;
    float gv[4];
    #pragma unroll
    for (int g = 0; g < 4; g++){
      int n = g*256 + j;
      float base = jl ? pg[g].y : pg[g].x;
      gv[g] = base + g_bias[n]
            + x0*g_Wx[n*OUTD+0] + x1*g_Wx[n*OUTD+1] + x2*g_Wx[n*OUTD+2];
    }
    float c  = g_c[b*Hh + j];
    float cn = sigmoidf_(gv[1])*c + sigmoidf_(gv[0])*tanhf(gv[2]);
    float hn = sigmoidf_(gv[3])*tanhf(cn);
    g_c[b*Hh + j] = cn;
    hnew[b*Hh + j] = hn;
  }
}

// ---------------------------------------------------------------- final: pred_63 + decoder_hidden
__global__ void __launch_bounds__(256)
k_final(const float* __restrict__ h, const float* __restrict__ Wo,
        const float* __restrict__ bo, float* __restrict__ out){
  __shared__ float h_s[Hh];
  int b = blockIdx.x, tid = threadIdx.x, wid = tid >> 5, lane = tid & 31;
  float hn = h[b*Hh + tid];
  h_s[tid] = hn;
  out[OFF_HID + b*Hh + tid] = hn;
  __syncthreads();
  if (wid < 3){
    float a = 0.f;
    #pragma unroll
    for (int k = lane; k < Hh; k += 32) a = fmaf(h_s[k], Wo[wid*Hh + k], a);
    a = warp_sum(a);
    if (!lane)
      out[OFF_PRED + ((size_t)b*NST + (NST-1))*OUTD + wid] = a + bo[wid];
  }
}

// ---------------------------------------------------------------- launch
extern "C" void kernel_launch(void* const* d_in, const int* in_sizes, int n_in,
                              void* d_out, int out_size){
  const float* enc  = (const float*)d_in[0];
  const float* ehid = (const float*)d_in[1];
  const float* ecell= (const float*)d_in[2];
  const float* Wa   = (const float*)d_in[3];
  const float* ba   = (const float*)d_in[4];
  const float* Ua   = (const float*)d_in[5];
  /* d_in[6] (bua): softmax-invariant, unused */
  const float* Wih  = (const float*)d_in[7];
  const float* Whh  = (const float*)d_in[8];
  const float* bih  = (const float*)d_in[9];
  const float* bhh  = (const float*)d_in[10];
  const float* Wo   = (const float*)d_in[11];
  const float* bo   = (const float*)d_in[12];
  float* out = (float*)d_out;

  float* hb0; cudaGetSymbolAddress((void**)&hb0, g_hbuf);
  float* hb1 = hb0 + Bb*Hh;

  cudaFuncSetAttribute(k_attn, cudaFuncAttributeMaxDynamicSharedMemorySize, ATTN_DSM);

  k_init<<<256, 256>>>(ehid, ecell);
  k_pack<<<G4, 512>>>(Wih, Whh, bih, bhh);
  k_prep<<<Hh + 1, 256>>>(Wa, ba, Ua);
  for (int t = 0; t < NST; t++){
    const float* hold = (t & 1) ? hb1 : hb0;
    float* hnew       = (t & 1) ? hb0 : hb1;
    k_attn<<<Bb, 256, ATTN_DSM>>>(enc, hold, Wo, bo, out, t);
    k_gl<<<128, 256>>>(hold, hnew);
  }
  k_final<<<256, 256>>>(hb0, Wo, bo, out);   // h after step 63 lives in hbuf[0]
}

// round 11
// speedup vs baseline: 1.0013x; 1.0013x over previous
#include <cuda_runtime.h>
#include <math.h>
#include <stdint.h>

// Problem dims
#define Bb   256
#define Ss   512
#define Hh   256
#define OUTD 3
#define NST  64
#define INW  259
#define G4   (4*Hh)
#define TR   16
#define NTILES (Ss/TR)   // 32

// Output layout
#define OFF_PRED 0
#define OFF_HID  (Bb*NST*OUTD)          // 49152
#define OFF_ATT  (OFF_HID + Bb*Hh)      // 114688

// Persistent device state
__device__ float g_hbuf[2][Bb*Hh];
__device__ float g_c[Bb*Hh];
__device__ float g_x[Bb*OUTD];
__device__ float g_ctx[Bb*Hh];
__device__ float g_WgT[512*G4];    // [k][col], col = (j'>>1)*8 + gate*2 + (j'&1)
__device__ float g_Wx[G4*OUTD];    // indexed by n = gate*256 + j'
__device__ float g_bias[G4];
__device__ float g_M[Hh*Hh];       // [k][j]
__device__ float g_vb[Hh];

__device__ __forceinline__ float warp_sum(float v){
  #pragma unroll
  for (int o = 16; o; o >>= 1) v += __shfl_xor_sync(0xffffffffu, v, o);
  return v;
}
__device__ __forceinline__ float sigmoidf_(float x){ return 1.f/(1.f+expf(-x)); }

__device__ __forceinline__ uint32_t smem_u32(const void* p){
  return (uint32_t)__cvta_generic_to_shared(p);
}
__device__ __forceinline__ void cp16(uint32_t dst, const void* src){
  asm volatile("cp.async.cg.shared.global [%0], [%1], 16;" :: "r"(dst), "l"(src));
}
#define CP_COMMIT() asm volatile("cp.async.commit_group;")
#define CP_WAIT(n)  asm volatile("cp.async.wait_group %0;" :: "n"(n))

__device__ __forceinline__ void fma2(unsigned long long &d, unsigned long long a, unsigned long long b){
  asm("fma.rn.f32x2 %0, %1, %2, %3;" : "=l"(d) : "l"(a), "l"(b), "l"(d));
}
__device__ __forceinline__ unsigned long long dup2(float v){
  unsigned long long r; uint32_t u = __float_as_uint(v);
  asm("mov.b64 %0, {%1, %1};" : "=l"(r) : "r"(u));
  return r;
}
__device__ __forceinline__ float2 unpack2(unsigned long long v){
  uint32_t lo, hi;
  asm("mov.b64 {%0, %1}, %2;" : "=r"(lo), "=r"(hi) : "l"(v));
  return make_float2(__uint_as_float(lo), __uint_as_float(hi));
}

// ---------------------------------------------------------------- init/pack/prep
__global__ void k_init(const float* __restrict__ eh, const float* __restrict__ ec){
  int i = blockIdx.x*blockDim.x + threadIdx.x;
  if (i < Bb*Hh){ g_hbuf[0][i] = eh[i]; g_c[i] = ec[i]; }
  if (i < Bb*OUTD) g_x[i] = 0.f;
}

__global__ void k_pack(const float* __restrict__ Wih, const float* __restrict__ Whh,
                       const float* __restrict__ bih, const float* __restrict__ bhh){
  int j = blockIdx.x;   // 0..1023, original row: gate g = j>>8, j' = j&255
  int k = threadIdx.x;  // 0..511
  float val = (k < Hh) ? Wih[j*INW + OUTD + k] : Whh[j*Hh + (k - Hh)];
  int g = j >> 8, jp = j & 255;
  int col = (jp >> 1)*8 + g*2 + (jp & 1);
  g_WgT[(size_t)k*G4 + col] = val;
  if (k < OUTD) g_Wx[j*OUTD + k] = Wih[j*INW + k];
  if (k == 0)   g_bias[j] = bih[j] + bhh[j];
}

__global__ void k_prep(const float* __restrict__ Wa, const float* __restrict__ ba,
                       const float* __restrict__ Ua){
  int kk = blockIdx.x, j = threadIdx.x;
  float a = 0.f;
  if (kk < Hh){
    #pragma unroll 4
    for (int g = 0; g < Hh; g++) a = fmaf(Wa[g*Hh + kk], Ua[g*Hh + j], a);
    g_M[kk*Hh + j] = a;
  } else {
    #pragma unroll 4
    for (int g = 0; g < Hh; g++) a = fmaf(ba[g], Ua[g*Hh + j], a);
    g_vb[j] = a;
  }
}

// ---------------------------------------------------------------- attention megaphase
// 1 block per batch. Prologue (under cp.async): pred(h)->x/out, v = h@M+vb.
// Then single-slice flash attention over 512 rows; writes FINAL weights + ctx.
#define ATTN_DSM (3*TR*Hh*4)   // 49152
__global__ void __launch_bounds__(256)
k_attn(const float* __restrict__ enc, const float* __restrict__ hold,
       const float* __restrict__ Wo, const float* __restrict__ bo,
       float* __restrict__ out, int t){
  extern __shared__ float tb[];          // [3][TR][Hh]
  __shared__ float h_s[Hh];
  __shared__ float v_s[Hh];
  __shared__ float ctx_s[Hh];
  __shared__ float wbuf[Ss];
  __shared__ float tsc[TR];
  __shared__ float tmaxs[NTILES];
  __shared__ float red0;
  int b = blockIdx.x, tid = threadIdx.x, wid = tid >> 5, lane = tid & 31;
  const float* encb = enc + (size_t)b*Ss*Hh;

  auto issue = [&](int ti){
    const float4* src = (const float4*)(encb + (size_t)ti*TR*Hh);
    uint32_t dst = smem_u32(tb + (ti % 3)*TR*Hh);
    #pragma unroll
    for (int i = 0; i < 4; i++){
      int idx = tid + 256*i;
      cp16(dst + idx*16, src + idx);
    }
    CP_COMMIT();
  };

  h_s[tid] = hold[b*Hh + tid];
  issue(0); issue(1); issue(2);
  ctx_s[tid] = 0.f;
  __syncthreads();

  // pred from h_t -> autoregressive x + output for step t-1
  if (wid < 3){
    float a = 0.f;
    #pragma unroll
    for (int k = lane; k < Hh; k += 32) a = fmaf(h_s[k], Wo[wid*Hh + k], a);
    a = warp_sum(a);
    if (!lane && t > 0){
      float p = a + bo[wid];
      out[OFF_PRED + ((size_t)b*NST + (t-1))*OUTD + wid] = p;
      g_x[b*OUTD + wid] = p;
    }
  }
  // v = h @ M + vb (coalesced L2 reads of M; overlaps enc prefetch)
  {
    float acc = g_vb[tid];
    #pragma unroll 16
    for (int k = 0; k < Hh; k++) acc = fmaf(h_s[k], g_M[k*Hh + tid], acc);
    v_s[tid] = acc;
  }
  __syncthreads();

  float m_run = -3.0e38f, l_run = 0.f;
  for (int ti = 0; ti < NTILES; ti++){
    int rem = NTILES - 1 - ti;
    if (rem >= 2)      CP_WAIT(2);
    else if (rem == 1) CP_WAIT(1);
    else               CP_WAIT(0);
    __syncthreads();
    const float* tile = tb + (ti % 3)*TR*Hh;

    // scores: 2 rows per warp
    #pragma unroll
    for (int r = 0; r < 2; r++){
      int s = wid*2 + r;
      float acc = 0.f;
      #pragma unroll
      for (int k = 0; k < 8; k++) acc = fmaf(tile[s*Hh + lane + 32*k], v_s[lane + 32*k], acc);
      acc = warp_sum(acc);
      if (!lane) tsc[s] = acc;
    }
    __syncthreads();

    float mt = tsc[0];
    #pragma unroll
    for (int s = 1; s < TR; s++) mt = fmaxf(mt, tsc[s]);
    float m_new = fmaxf(m_run, mt);
    float scale = expf(m_run - m_new);

    if (wid == 0){
      float e = (lane < TR) ? expf(tsc[lane] - m_new) : 0.f;
      if (lane < TR) wbuf[ti*TR + lane] = e;
      float es = warp_sum(e);
      if (!lane){ red0 = es; tmaxs[ti] = m_new; }
    }
    __syncthreads();
    l_run = l_run * scale + red0;
    m_run = m_new;

    float c = ctx_s[tid] * scale;
    #pragma unroll
    for (int s = 0; s < TR; s++) c = fmaf(wbuf[ti*TR + s], tile[s*Hh + tid], c);
    ctx_s[tid] = c;
    __syncthreads();                     // tile (ti%3) free
    if (ti + 3 < NTILES) issue(ti + 3);
  }

  float inv = 1.f / l_run;
  g_ctx[b*Hh + tid] = ctx_s[tid] * inv;
  float* att = out + OFF_ATT + ((size_t)b*NST + t)*Ss;
  att[tid]        = wbuf[tid]       * expf(tmaxs[tid >> 4] - m_run)       * inv;
  att[tid + 256]  = wbuf[tid + 256] * expf(tmaxs[(tid + 256) >> 4] - m_run) * inv;
}

// ---------------------------------------------------------------- gates GEMM + fused LSTM (f32x2)
// 128 blocks x 256 thr: jt = p&15 (16 j'), mt = p>>4 (32 batches).
// Thread (tx 0..7, ty 0..31): 1 batch, j-pair j0+tx*2, all 4 gates.
#define GKT 32
__global__ void __launch_bounds__(256)
k_gl(const float* __restrict__ hold, float* __restrict__ hnew){
  __shared__ __align__(16) float As[2][GKT*36];
  __shared__ __align__(16) float Bs[2][GKT*64];
  int p = blockIdx.x, tid = threadIdx.x;
  int jt = p & 15, mt = p >> 4;
  int j0 = jt * 16, m0 = mt * 32;

  auto issueB = [&](int it){
    int kt = it*GKT, pb = it & 1;
    #pragma unroll
    for (int i = 0; i < 2; i++){
      int idx = tid + 256*i;            // 512 cp16 (32 rows x 64 floats)
      int row = idx >> 4, c4 = (idx & 15) << 2;
      cp16(smem_u32(&Bs[pb][row*64 + c4]),
           g_WgT + (size_t)(kt + row)*G4 + jt*64 + c4);
    }
    CP_COMMIT();
  };
  auto loadA = [&](int it){
    int kt = it*GKT, pb = it & 1;
    int rr = tid >> 3, c4 = (tid & 7) << 2;   // batch, local k
    int bb = m0 + rr, k = kt + c4;
    float4 a4 = (k < Hh) ? *(const float4*)(g_ctx + bb*Hh + k)
                         : *(const float4*)(hold  + bb*Hh + (k - Hh));
    As[pb][(c4+0)*36 + rr] = a4.x;
    As[pb][(c4+1)*36 + rr] = a4.y;
    As[pb][(c4+2)*36 + rr] = a4.z;
    As[pb][(c4+3)*36 + rr] = a4.w;
  };

  int tx = tid & 7, ty = tid >> 3;
  unsigned long long acc2[4] = {};      // per gate: f32x2 over (j_lo, j_hi)

  issueB(0); loadA(0);
  for (int it = 0; it < 16; it++){
    if (it < 15){ issueB(it+1); loadA(it+1); CP_WAIT(1); }
    else          CP_WAIT(0);
    __syncthreads();
    int pb = it & 1;
    #pragma unroll
    for (int kk = 0; kk < GKT; kk++){
      unsigned long long a = dup2(As[pb][kk*36 + ty]);
      ulonglong2 b01 = *(const ulonglong2*)&Bs[pb][kk*64 + tx*8];
      ulonglong2 b23 = *(const ulonglong2*)&Bs[pb][kk*64 + tx*8 + 4];
      fma2(acc2[0], a, b01.x);
      fma2(acc2[1], a, b01.y);
      fma2(acc2[2], a, b23.x);
      fma2(acc2[3], a, b23.y);
    }
    __syncthreads();
  }

  // fused LSTM: this thread owns batch b, j in {j0+tx*2, j0+tx*2+1}, all gates
  int b = m0 + ty;
  float x0 = g_x[b*OUTD+0], x1 = g_x[b*OUTD+1], x2 = g_x[b*OUTD+2];
  float2 pg[4];
  #pragma unroll
  for (int g = 0; g < 4; g++) pg[g] = unpack2(acc2[g]);
  #pragma unroll
  for (int jl = 0; jl < 2; jl++){
    int j = j0 + tx*2 + jl;
    float gv[4];
    #pragma unroll
    for (int g = 0; g < 4; g++){
      int n = g*256 + j;
      float base = jl ? pg[g].y : pg[g].x;
      gv[g] = base + g_bias[n]
            + x0*g_Wx[n*OUTD+0] + x1*g_Wx[n*OUTD+1] + x2*g_Wx[n*OUTD+2];
    }
    float c  = g_c[b*Hh + j];
    float cn = sigmoidf_(gv[1])*c + sigmoidf_(gv[0])*tanhf(gv[2]);
    float hn = sigmoidf_(gv[3])*tanhf(cn);
    g_c[b*Hh + j] = cn;
    hnew[b*Hh + j] = hn;
  }
}

// ---------------------------------------------------------------- final: pred_63 + decoder_hidden
__global__ void __launch_bounds__(256)
k_final(const float* __restrict__ h, const float* __restrict__ Wo,
        const float* __restrict__ bo, float* __restrict__ out){
  __shared__ float h_s[Hh];
  int b = blockIdx.x, tid = threadIdx.x, wid = tid >> 5, lane = tid & 31;
  float hn = h[b*Hh + tid];
  h_s[tid] = hn;
  out[OFF_HID + b*Hh + tid] = hn;
  __syncthreads();
  if (wid < 3){
    float a = 0.f;
    #pragma unroll
    for (int k = lane; k < Hh; k += 32) a = fmaf(h_s[k], Wo[wid*Hh + k], a);
    a = warp_sum(a);
    if (!lane)
      out[OFF_PRED + ((size_t)b*NST + (NST-1))*OUTD + wid] = a + bo[wid];
  }
}

// ---------------------------------------------------------------- launch
extern "C" void kernel_launch(void* const* d_in, const int* in_sizes, int n_in,
                              void* d_out, int out_size){
  const float* enc  = (const float*)d_in[0];
  const float* ehid = (const float*)d_in[1];
  const float* ecell= (const float*)d_in[2];
  const float* Wa   = (const float*)d_in[3];
  const float* ba   = (const float*)d_in[4];
  const float* Ua   = (const float*)d_in[5];
  /* d_in[6] (bua): softmax-invariant, unused */
  const float* Wih  = (const float*)d_in[7];
  const float* Whh  = (const float*)d_in[8];
  const float* bih  = (const float*)d_in[9];
  const float* bhh  = (const float*)d_in[10];
  const float* Wo   = (const float*)d_in[11];
  const float* bo   = (const float*)d_in[12];
  float* out = (float*)d_out;

  float* hb0; cudaGetSymbolAddress((void**)&hb0, g_hbuf);
  float* hb1 = hb0 + Bb*Hh;

  cudaFuncSetAttribute(k_attn, cudaFuncAttributeMaxDynamicSharedMemorySize, ATTN_DSM);

  k_init<<<256, 256>>>(ehid, ecell);
  k_pack<<<G4, 512>>>(Wih, Whh, bih, bhh);
  k_prep<<<Hh + 1, 256>>>(Wa, ba, Ua);
  for (int t = 0; t < NST; t++){
    const float* hold = (t & 1) ? hb1 : hb0;
    float* hnew       = (t & 1) ? hb0 : hb1;
    k_attn<<<Bb, 256, ATTN_DSM>>>(enc, hold, Wo, bo, out, t);
    k_gl<<<128, 256>>>(hold, hnew);
  }
  k_final<<<256, 256>>>(hb0, Wo, bo, out);   // h after step 63 lives in hbuf[0]
}